// round 9
// baseline (speedup 1.0000x reference)
#include <cuda_runtime.h>
#include <cuda_bf16.h>
#include <math.h>

#define BB   2
#define TT   1024
#define CC   2048
#define NH   16
#define HS   128
#define NLQ  512
#define NLKV 512
#define DHR  64
#define KCAT 576

// ---------------- scratch ----------------
__device__ float g_keff[16l * 512 * 512];       // keff_t[h][k][q] (q contiguous)
__device__ float g_veff[2048l * 512];           // veff_t[j][k]   (k contiguous)
__device__ float g_cq  [2048l * 512];
__device__ float g_ckr [2048l * 64];
__device__ float g_cqr [2048l * 1024];
__device__ float g_kcat[2048l * 576];
__device__ float g_qcat[32l * 1024 * 576];
__device__ float g_attn[32l * 1024 * 1024];
__device__ float g_lat [32l * 1024 * 512];

struct GP {
    const float* A; const float* B; float* C;
    int M, N, K;
    long sAm, sAk, sBk, sBn, ldc;
    int aDiv, aMod, bDiv, bMod, cDiv, cMod;
    long aS1, aS2, bS1, bS2, cS1, cS2;
    int kSplit;
    int mode;    // 0 plain, 1 causal tile-skip, 2 causal k-stop
};

__device__ __forceinline__ unsigned f2tf32(float x) {
    unsigned u;
    asm("cvt.rna.tf32.f32 %0, %1;" : "=r"(u) : "f"(x));
    return u;
}

__device__ __forceinline__ void mma_tf32(float* d, const unsigned* a,
                                         const unsigned* b) {
    asm volatile(
        "mma.sync.aligned.m16n8k8.row.col.f32.tf32.tf32.f32 "
        "{%0,%1,%2,%3}, {%4,%5,%6,%7}, {%8,%9}, {%0,%1,%2,%3};\n"
        : "+f"(d[0]), "+f"(d[1]), "+f"(d[2]), "+f"(d[3])
        : "r"(a[0]), "r"(a[1]), "r"(a[2]), "r"(a[3]),
          "r"(b[0]), "r"(b[1]));
}

// smem words/buffer: contiguous [m][12] = 1536; non-contig [k][136] = 1088
#define BUFW 1536

// TF32 GEMM: block 128x128, k-tile 8, 4 warps (2x2), warp tile 64x64,
// double-buffered smem + 2-deep register prefetch, vectorized STS,
// split-K + causal modes.
__global__ __launch_bounds__(128) void tgemm(GP p) {
    int bmI = blockIdx.y, bnI = blockIdx.x;
    if (p.mode == 1 && bnI > bmI) return;

    int z = blockIdx.z;
    int zb = z / p.kSplit;
    int kz = z % p.kSplit;

    int kTot = p.K;
    if (p.mode == 2) { int ke = (bmI + 1) * 128; if (ke < kTot) kTot = ke; }
    int kLen = kTot / p.kSplit;

    const float* A = p.A + (long)(zb / p.aDiv) * p.aS1 + (long)(zb % p.aMod) * p.aS2
                   + (long)kz * kLen * p.sAk;
    const float* B = p.B + (long)(zb / p.bDiv) * p.bS1 + (long)(zb % p.bMod) * p.bS2
                   + (long)kz * kLen * p.sBk;
    float*       C = p.C + (long)(zb / p.cDiv) * p.cS1 + (long)(zb % p.cMod) * p.cS2;

    __shared__ __align__(16) unsigned As[2][BUFW];
    __shared__ __align__(16) unsigned Bs[2][BUFW];

    int tid  = threadIdx.x;
    int lane = tid & 31;
    int wid  = tid >> 5;
    int wm = wid >> 1, wn = wid & 1;
    int bm = bmI * 128, bn = bnI * 128;

    const bool aKc = (p.sAk == 1);
    const bool bKc = (p.sBk == 1);

    const unsigned SaM = aKc ? 12u : 1u,  SaK = aKc ? 1u : 136u;
    const unsigned SbN = bKc ? 12u : 1u,  SbK = bKc ? 1u : 136u;

    const float* aBase;  long aStep;  unsigned aOff;
    if (aKc) {
        aBase = A + (long)(bm + tid) * p.sAm;
        aStep = 8;
        aOff  = tid * 12;
    } else {
        int k8 = tid >> 4, m0 = (tid & 15) * 8;
        aBase = A + (long)k8 * p.sAk + (bm + m0);
        aStep = 8 * p.sAk;
        aOff  = k8 * 136 + m0;
    }
    const float* bBase;  long bStep;  unsigned bOff;  bool bOk;
    if (bKc) {
        bOk = (bn + tid) < p.N;
        bBase = B + (long)(bn + tid) * p.sBn;
        bStep = 8;
        bOff  = tid * 12;
    } else {
        int k8 = tid >> 4, n0 = (tid & 15) * 8;
        bOk = (bn + n0) < p.N;
        bBase = B + (long)k8 * p.sBk + (bn + n0);
        bStep = 8 * p.sBk;
        bOff  = k8 * 136 + n0;
    }

    // two register staging sets
    float ra[2][8], rb[2][8];

#define LOAD_STAGE(t, s)                                                     \
    {                                                                        \
        const float* ap = aBase + (long)(t) * aStep;                         \
        float4 v0 = *(const float4*)ap;                                      \
        float4 v1 = *(const float4*)(ap + 4);                                \
        ra[s][0]=v0.x; ra[s][1]=v0.y; ra[s][2]=v0.z; ra[s][3]=v0.w;          \
        ra[s][4]=v1.x; ra[s][5]=v1.y; ra[s][6]=v1.z; ra[s][7]=v1.w;          \
        if (bOk) {                                                           \
            const float* bp = bBase + (long)(t) * bStep;                     \
            float4 w0 = *(const float4*)bp;                                  \
            float4 w1 = *(const float4*)(bp + 4);                            \
            rb[s][0]=w0.x; rb[s][1]=w0.y; rb[s][2]=w0.z; rb[s][3]=w0.w;      \
            rb[s][4]=w1.x; rb[s][5]=w1.y; rb[s][6]=w1.z; rb[s][7]=w1.w;      \
        } else {                                                             \
            rb[s][0]=rb[s][1]=rb[s][2]=rb[s][3]=0.f;                         \
            rb[s][4]=rb[s][5]=rb[s][6]=rb[s][7]=0.f;                         \
        }                                                                    \
    }

#define STORE_STAGE(buf, s)                                                  \
    {                                                                        \
        uint4 va0, va1, vb0, vb1;                                            \
        va0.x=f2tf32(ra[s][0]); va0.y=f2tf32(ra[s][1]);                      \
        va0.z=f2tf32(ra[s][2]); va0.w=f2tf32(ra[s][3]);                      \
        va1.x=f2tf32(ra[s][4]); va1.y=f2tf32(ra[s][5]);                      \
        va1.z=f2tf32(ra[s][6]); va1.w=f2tf32(ra[s][7]);                      \
        vb0.x=f2tf32(rb[s][0]); vb0.y=f2tf32(rb[s][1]);                      \
        vb0.z=f2tf32(rb[s][2]); vb0.w=f2tf32(rb[s][3]);                      \
        vb1.x=f2tf32(rb[s][4]); vb1.y=f2tf32(rb[s][5]);                      \
        vb1.z=f2tf32(rb[s][6]); vb1.w=f2tf32(rb[s][7]);                      \
        *(uint4*)&As[buf][aOff]     = va0;                                   \
        *(uint4*)&As[buf][aOff + 4] = va1;                                   \
        *(uint4*)&Bs[buf][bOff]     = vb0;                                   \
        *(uint4*)&Bs[buf][bOff + 4] = vb1;                                   \
    }

    float acc[4][8][4];
#pragma unroll
    for (int i = 0; i < 4; i++)
#pragma unroll
        for (int j = 0; j < 8; j++)
#pragma unroll
            for (int r = 0; r < 4; r++) acc[i][j][r] = 0.f;

    int nt = kLen >> 3;

    // prologue: tile0 -> reg0 -> buf0; tile1 -> reg1 (STS'd inside loop at t=0)
    LOAD_STAGE(0, 0);
    STORE_STAGE(0, 0);
    if (nt > 1) LOAD_STAGE(1, 1);
    __syncthreads();

    int r = lane >> 2, c = lane & 3;

    unsigned aAddr[4], bAddr[8];
#pragma unroll
    for (int mi = 0; mi < 4; mi++)
        aAddr[mi] = (unsigned)(wm * 64 + mi * 16 + r) * SaM + (unsigned)c * SaK;
#pragma unroll
    for (int ni = 0; ni < 8; ni++)
        bAddr[ni] = (unsigned)(wn * 64 + ni * 8 + r) * SbN + (unsigned)c * SbK;
    const unsigned a8 = 8u * SaM, a4k = 4u * SaK, b4k = 4u * SbK;

    for (int t = 0; t < nt; t++) {
        int cur = t & 1;
        // issue LDG for t+2 first (into the reg set freed by last iteration's STS)
        if (t + 2 < nt) LOAD_STAGE(t + 2, cur);

        unsigned a[4][4], b[8][2];
#pragma unroll
        for (int mi = 0; mi < 4; mi++) {
            const unsigned* sa = &As[cur][0];
            unsigned o = aAddr[mi];
            a[mi][0] = sa[o];
            a[mi][1] = sa[o + a8];
            a[mi][2] = sa[o + a4k];
            a[mi][3] = sa[o + a8 + a4k];
        }
#pragma unroll
        for (int ni = 0; ni < 8; ni++) {
            const unsigned* sb = &Bs[cur][0];
            unsigned o = bAddr[ni];
            b[ni][0] = sb[o];
            b[ni][1] = sb[o + b4k];
        }
#pragma unroll
        for (int mi = 0; mi < 4; mi++)
#pragma unroll
            for (int ni = 0; ni < 8; ni++)
                mma_tf32(acc[mi][ni], a[mi], b[ni]);

        // STS tile t+1 from the reg set loaded one full iteration ago
        if (t + 1 < nt) STORE_STAGE(cur ^ 1, cur ^ 1);
        __syncthreads();
    }

    int c2 = (lane & 3) * 2;
    if (p.kSplit > 1) {
#pragma unroll
        for (int mi = 0; mi < 4; mi++) {
            int gm0 = bm + wm * 64 + mi * 16 + r;
#pragma unroll
            for (int ni = 0; ni < 8; ni++) {
                int gn = bn + wn * 64 + ni * 8 + c2;
                if (gn < p.N) {
                    atomicAdd(C + (long)gm0 * p.ldc + gn,     acc[mi][ni][0]);
                    atomicAdd(C + (long)gm0 * p.ldc + gn + 1, acc[mi][ni][1]);
                    atomicAdd(C + (long)(gm0 + 8) * p.ldc + gn,     acc[mi][ni][2]);
                    atomicAdd(C + (long)(gm0 + 8) * p.ldc + gn + 1, acc[mi][ni][3]);
                }
            }
        }
    } else {
#pragma unroll
        for (int mi = 0; mi < 4; mi++) {
            int gm0 = bm + wm * 64 + mi * 16 + r;
#pragma unroll
            for (int ni = 0; ni < 8; ni++) {
                int gn = bn + wn * 64 + ni * 8 + c2;
                if (gn < p.N) {
                    float* cp0 = C + (long)gm0 * p.ldc + gn;
                    float* cp1 = C + (long)(gm0 + 8) * p.ldc + gn;
                    cp0[0] = acc[mi][ni][0]; cp0[1] = acc[mi][ni][1];
                    cp1[0] = acc[mi][ni][2]; cp1[1] = acc[mi][ni][3];
                }
            }
        }
    }
#undef LOAD_STAGE
#undef STORE_STAGE
}

// ---------------- RoPE ----------------
__global__ void rope_k_kernel(const float* __restrict__ ckr,
                              const float* __restrict__ fc,
                              const float* __restrict__ fs,
                              float* __restrict__ kcat) {
    int idx = blockIdx.x * blockDim.x + threadIdx.x;
    if (idx >= 2048 * 32) return;
    int m = idx >> 5, i = idx & 31;
    int t = m & 1023;
    float re = ckr[m * 64 + 2 * i], im = ckr[m * 64 + 2 * i + 1];
    float c = fc[t * 32 + i], s = fs[t * 32 + i];
    long o = (long)m * KCAT + 512 + 2 * i;
    kcat[o]     = re * c - im * s;
    kcat[o + 1] = re * s + im * c;
}

__global__ void rope_q_kernel(const float* __restrict__ cqr,
                              const float* __restrict__ fc,
                              const float* __restrict__ fs,
                              float* __restrict__ qcat) {
    int idx = blockIdx.x * blockDim.x + threadIdx.x;
    if (idx >= 2048 * 16 * 32) return;
    int i = idx & 31;
    int h = (idx >> 5) & 15;
    int m = idx >> 9;
    int t = m & 1023, b = m >> 10;
    float re = cqr[m * 1024 + h * 64 + 2 * i];
    float im = cqr[m * 1024 + h * 64 + 2 * i + 1];
    float c = fc[t * 32 + i], s = fs[t * 32 + i];
    long o = ((long)((b * 16 + h) * 1024 + t)) * KCAT + 512 + 2 * i;
    qcat[o]     = re * c - im * s;
    qcat[o + 1] = re * s + im * c;
}

// ---------------- causal softmax ----------------
__global__ void softmax_causal(float* __restrict__ attn) {
    int t = blockIdx.x;
    int z = blockIdx.y;
    float* p = attn + (long)z * 1024 * 1024 + (long)t * 1024;
    int n = t + 1;
    int lim = ((t >> 7) + 1) << 7;
    const float scale = 0.07216878364870322992f * 1.44269504088896341f;
    __shared__ float red[256];
    int tid = threadIdx.x;

    float vals[4];
    float m = -3.4e38f;
#pragma unroll
    for (int j = 0; j < 4; j++) {
        int s = tid + j * 256;
        vals[j] = (s < n) ? p[s] * scale : -3.4e38f;
        m = fmaxf(m, vals[j]);
    }
    red[tid] = m; __syncthreads();
    for (int o = 128; o > 0; o >>= 1) {
        if (tid < o) red[tid] = fmaxf(red[tid], red[tid + o]);
        __syncthreads();
    }
    m = red[0]; __syncthreads();

    float sum = 0.f;
#pragma unroll
    for (int j = 0; j < 4; j++) {
        int s = tid + j * 256;
        vals[j] = (s < n) ? exp2f(vals[j] - m) : 0.f;
        sum += vals[j];
    }
    red[tid] = sum; __syncthreads();
    for (int o = 128; o > 0; o >>= 1) {
        if (tid < o) red[tid] += red[tid + o];
        __syncthreads();
    }
    float inv = 1.f / red[0];

#pragma unroll
    for (int j = 0; j < 4; j++) {
        int s = tid + j * 256;
        if (s < lim) p[s] = vals[j] * inv;
    }
}

// ---------------- launch helper ----------------
static void launch_gemm(const float* A, const float* B, float* C,
                        int M, int N, int K,
                        long sAm, long sAk, long sBk, long sBn, long ldc,
                        int batches,
                        int aDiv, long aS1, int aMod, long aS2,
                        int bDiv, long bS1, int bMod, long bS2,
                        int cDiv, long cS1, int cMod, long cS2,
                        int kSplit = 1, int mode = 0) {
    GP p;
    p.A = A; p.B = B; p.C = C;
    p.M = M; p.N = N; p.K = K;
    p.sAm = sAm; p.sAk = sAk; p.sBk = sBk; p.sBn = sBn; p.ldc = ldc;
    p.aDiv = aDiv; p.aMod = aMod; p.bDiv = bDiv; p.bMod = bMod;
    p.cDiv = cDiv; p.cMod = cMod;
    p.aS1 = aS1; p.aS2 = aS2; p.bS1 = bS1; p.bS2 = bS2; p.cS1 = cS1; p.cS2 = cS2;
    p.kSplit = kSplit; p.mode = mode;
    dim3 grid((N + 127) / 128, (M + 127) / 128, batches * kSplit);
    tgemm<<<grid, 128>>>(p);
}

extern "C" void kernel_launch(void* const* d_in, const int* in_sizes, int n_in,
                              void* d_out, int out_size) {
    const float* x     = (const float*)d_in[0];
    const float* fcos  = (const float*)d_in[1];
    const float* fsin  = (const float*)d_in[2];
    const float* W_dq  = (const float*)d_in[3];
    const float* W_uq  = (const float*)d_in[4];
    const float* W_dkv = (const float*)d_in[5];
    const float* W_uk  = (const float*)d_in[6];
    const float* W_uv  = (const float*)d_in[7];
    const float* W_qr  = (const float*)d_in[8];
    const float* W_kr  = (const float*)d_in[9];
    const float* W_o   = (const float*)d_in[10];
    float* out = (float*)d_out;

    float *keff, *veff, *cq, *ckr, *cqr, *kcat, *qcat, *attn, *lat;
    cudaGetSymbolAddress((void**)&keff, g_keff);
    cudaGetSymbolAddress((void**)&veff, g_veff);
    cudaGetSymbolAddress((void**)&cq,   g_cq);
    cudaGetSymbolAddress((void**)&ckr,  g_ckr);
    cudaGetSymbolAddress((void**)&cqr,  g_cqr);
    cudaGetSymbolAddress((void**)&kcat, g_kcat);
    cudaGetSymbolAddress((void**)&qcat, g_qcat);
    cudaGetSymbolAddress((void**)&attn, g_attn);
    cudaGetSymbolAddress((void**)&lat,  g_lat);

    cudaMemsetAsync(veff, 0, 2048l * 512 * 4);
    cudaMemsetAsync(cq,   0, 2048l * 512 * 4);
    cudaMemsetAsync(ckr,  0, 2048l * 64 * 4);
    cudaMemsetAsync(cqr,  0, 2048l * 1024 * 4);
    cudaMemsetAsync(kcat, 0, 2048l * 576 * 4);

    // 1) keff_t[h][k][q]
    launch_gemm(W_uk, W_uq, keff, 512, 512, 128,
                1, 512, 1, 2048, 512, 16,
                1, 0, 16, 128l * 512,
                1, 0, 16, 128,
                1, 0, 16, 512l * 512);

    // 2) veff_t[j][k]  (split-K 4)
    launch_gemm(W_o, W_uv, veff, 2048, 512, 2048,
                2048, 1, 512, 1, 512, 1,
                1, 0, 1, 0, 1, 0, 1, 0, 1, 0, 1, 0, 4);

    // 3) c_q  (split-K 4)
    launch_gemm(x, W_dq, cq, 2048, 512, 2048,
                2048, 1, 1, 2048, 512, 1,
                1, 0, 1, 0, 1, 0, 1, 0, 1, 0, 1, 0, 4);

    // 4) c_kv -> kcat cols [0,512)  (split-K 4)
    launch_gemm(x, W_dkv, kcat, 2048, 512, 2048,
                2048, 1, 1, 2048, KCAT, 1,
                1, 0, 1, 0, 1, 0, 1, 0, 1, 0, 1, 0, 4);

    // 5) c_kr  (split-K 8)
    launch_gemm(x, W_kr, ckr, 2048, 64, 2048,
                2048, 1, 1, 2048, 64, 1,
                1, 0, 1, 0, 1, 0, 1, 0, 1, 0, 1, 0, 8);

    // 6) c_qr  (split-K 2)
    launch_gemm(cq, W_qr, cqr, 2048, 1024, 512,
                512, 1, 1, 512, 1024, 1,
                1, 0, 1, 0, 1, 0, 1, 0, 1, 0, 1, 0, 2);

    // 7-8) RoPE
    rope_k_kernel<<<(2048 * 32 + 255) / 256, 256>>>(ckr, fcos, fsin, kcat);
    rope_q_kernel<<<(2048 * 16 * 32 + 255) / 256, 256>>>(cqr, fcos, fsin, qcat);

    // 9) q_abs (B contiguous via keff_t)
    launch_gemm(cq, keff, qcat, 1024, 512, 512,
                512, 1, 1, 512, KCAT, 32,
                16, 1024l * 512, 1, 0,
                1, 0, 16, 512l * 512,
                1, 0, 32, 1024l * KCAT);

    // 10) logits (causal tile-skip)
    launch_gemm(qcat, kcat, attn, 1024, 1024, KCAT,
                KCAT, 1, 1, KCAT, 1024, 32,
                1, 0, 32, 1024l * KCAT,
                16, 1024l * KCAT, 1, 0,
                1, 0, 32, 1024l * 1024, 1, 1);

    // 11) softmax
    {
        dim3 grid(1024, 32);
        softmax_causal<<<grid, 256>>>(attn);
    }

    // 12) lat (causal k-stop)
    launch_gemm(attn, kcat, lat, 1024, 512, 1024,
                1024, 1, KCAT, 1, 512, 32,
                1, 0, 32, 1024l * 1024,
                16, 1024l * KCAT, 1, 0,
                1, 0, 32, 1024l * 512, 1, 2);

    // 13) y = lat @ veff_t^T
    launch_gemm(lat, veff, out, 1024, 128, 512,
                512, 1, 1, 512, 2048, 32,
                1, 0, 32, 1024l * 512,
                1, 0, 16, 128l * 512,
                16, 1024l * 2048, 16, 128);
}

// round 11
// speedup vs baseline: 1.6881x; 1.6881x over previous
#include <cuda_runtime.h>
#include <cuda_bf16.h>
#include <math.h>

#define BB   2
#define TT   1024
#define CC   2048
#define NH   16
#define HS   128
#define NLQ  512
#define NLKV 512
#define DHR  64
#define KCAT 576

// ---------------- scratch ----------------
__device__ float g_keff[16l * 512 * 512];       // keff_t[h][k][q] (q contiguous)
__device__ float g_veff[2048l * 512];           // veff_t[j][k]   (k contiguous)
__device__ float g_cq  [2048l * 512];
__device__ float g_ckr [2048l * 64];
__device__ float g_cqr [2048l * 1024];
__device__ float g_kcat[2048l * 576];
__device__ float g_qcat[32l * 1024 * 576];
__device__ float g_attn[32l * 1024 * 1024];
__device__ float g_lat [32l * 1024 * 512];

struct GP {
    const float* A; const float* B; float* C;
    int M, N, K;
    long sAm, sAk, sBk, sBn, ldc;
    int aDiv, aMod, bDiv, bMod, cDiv, cMod;
    long aS1, aS2, bS1, bS2, cS1, cS2;
    int kSplit;
    int mode;    // 0 plain, 1 causal tile-skip, 2 causal k-stop
};

__device__ __forceinline__ unsigned f2tf32(float x) {
    unsigned u;
    asm("cvt.rna.tf32.f32 %0, %1;" : "=r"(u) : "f"(x));
    return u;
}

__device__ __forceinline__ void mma_tf32(float* d, const unsigned* a,
                                         const unsigned* b) {
    asm volatile(
        "mma.sync.aligned.m16n8k8.row.col.f32.tf32.tf32.f32 "
        "{%0,%1,%2,%3}, {%4,%5,%6,%7}, {%8,%9}, {%0,%1,%2,%3};\n"
        : "+f"(d[0]), "+f"(d[1]), "+f"(d[2]), "+f"(d[3])
        : "r"(a[0]), "r"(a[1]), "r"(a[2]), "r"(a[3]),
          "r"(b[0]), "r"(b[1]));
}

#define CP16(dst, src) \
    asm volatile("cp.async.cg.shared.global [%0], [%1], 16;" \
                 :: "r"(dst), "l"(src))
#define CP_COMMIT() asm volatile("cp.async.commit_group;" ::: "memory")
#define CP_WAIT1()  asm volatile("cp.async.wait_group 1;" ::: "memory")

// smem words/buffer: contiguous [m][12] = 1536; non-contig [k][136] = 1088
#define BUFW   1536
#define STAGES 3

// TF32 GEMM: block 128x128, k-tile 8, 4 warps (2x2), warp tile 64x64,
// 3-stage cp.async pipeline (gmem->smem, no register staging),
// tf32 conversion in the consumer, split-K + causal modes.
__global__ __launch_bounds__(128) void tgemm(GP p) {
    int bmI = blockIdx.y, bnI = blockIdx.x;
    if (p.mode == 1 && bnI > bmI) return;

    int z = blockIdx.z;
    int zb = z / p.kSplit;
    int kz = z % p.kSplit;

    int kTot = p.K;
    if (p.mode == 2) { int ke = (bmI + 1) * 128; if (ke < kTot) kTot = ke; }
    int kLen = kTot / p.kSplit;

    const float* A = p.A + (long)(zb / p.aDiv) * p.aS1 + (long)(zb % p.aMod) * p.aS2
                   + (long)kz * kLen * p.sAk;
    const float* B = p.B + (long)(zb / p.bDiv) * p.bS1 + (long)(zb % p.bMod) * p.bS2
                   + (long)kz * kLen * p.sBk;
    float*       C = p.C + (long)(zb / p.cDiv) * p.cS1 + (long)(zb % p.cMod) * p.cS2;

    __shared__ __align__(16) float As[STAGES][BUFW];
    __shared__ __align__(16) float Bs[STAGES][BUFW];

    int tid  = threadIdx.x;
    int lane = tid & 31;
    int wid  = tid >> 5;
    int wm = wid >> 1, wn = wid & 1;
    int bm = bmI * 128, bn = bnI * 128;

    const bool aKc = (p.sAk == 1);
    const bool bKc = (p.sBk == 1);

    const unsigned SaM = aKc ? 12u : 1u,  SaK = aKc ? 1u : 136u;
    const unsigned SbN = bKc ? 12u : 1u,  SbK = bKc ? 1u : 136u;

    const float* aBase;  long aStep;  unsigned aOff;
    if (aKc) {
        aBase = A + (long)(bm + tid) * p.sAm;
        aStep = 8;
        aOff  = tid * 12;
    } else {
        int k8 = tid >> 4, m0 = (tid & 15) * 8;
        aBase = A + (long)k8 * p.sAk + (bm + m0);
        aStep = 8 * p.sAk;
        aOff  = k8 * 136 + m0;
    }
    const float* bBase;  long bStep;  unsigned bOff;  bool bOk;
    if (bKc) {
        bOk = (bn + tid) < p.N;
        bBase = B + (long)(bn + tid) * p.sBn;
        bStep = 8;
        bOff  = tid * 12;
    } else {
        int k8 = tid >> 4, n0 = (tid & 15) * 8;
        bOk = (bn + n0) < p.N;
        bBase = B + (long)k8 * p.sBk + (bn + n0);
        bStep = 8 * p.sBk;
        bOff  = k8 * 136 + n0;
    }

    // per-thread smem byte addresses (loop-invariant)
    unsigned aSm[STAGES], bSm[STAGES];
#pragma unroll
    for (int s = 0; s < STAGES; s++) {
        aSm[s] = (unsigned)__cvta_generic_to_shared(&As[s][aOff]);
        bSm[s] = (unsigned)__cvta_generic_to_shared(&Bs[s][bOff]);
    }

#define FETCH(t, slot)                                                       \
    do {                                                                     \
        const float* ap = aBase + (long)(t) * aStep;                         \
        CP16(aSm[slot],      ap);                                            \
        CP16(aSm[slot] + 16, ap + 4);                                        \
        if (bOk) {                                                           \
            const float* bp = bBase + (long)(t) * bStep;                     \
            CP16(bSm[slot],      bp);                                        \
            CP16(bSm[slot] + 16, bp + 4);                                    \
        }                                                                    \
        CP_COMMIT();                                                         \
    } while (0)

    float acc[4][8][4];
#pragma unroll
    for (int i = 0; i < 4; i++)
#pragma unroll
        for (int j = 0; j < 8; j++)
#pragma unroll
            for (int r = 0; r < 4; r++) acc[i][j][r] = 0.f;

    int nt = kLen >> 3;

    // prologue: stages 0,1 in flight
    FETCH(0, 0);
    if (nt > 1) {
        FETCH(1, 1);
    } else {
        CP_COMMIT();
    }

    int r = lane >> 2, c = lane & 3;

    unsigned aAddr[4], bAddr[8];
#pragma unroll
    for (int mi = 0; mi < 4; mi++)
        aAddr[mi] = (unsigned)(wm * 64 + mi * 16 + r) * SaM + (unsigned)c * SaK;
#pragma unroll
    for (int ni = 0; ni < 8; ni++)
        bAddr[ni] = (unsigned)(wn * 64 + ni * 8 + r) * SbN + (unsigned)c * SbK;
    const unsigned a8 = 8u * SaM, a4k = 4u * SaK, b4k = 4u * SbK;

    int slot = 0;
    for (int t = 0; t < nt; t++) {
        CP_WAIT1();            // group t complete (<=1 pending)
        __syncthreads();       // visible to all warps; also fences slot reuse

        const float* sa = &As[slot][0];
        const float* sb = &Bs[slot][0];
        unsigned a[4][4], b[8][2];
#pragma unroll
        for (int mi = 0; mi < 4; mi++) {
            unsigned o = aAddr[mi];
            a[mi][0] = f2tf32(sa[o]);
            a[mi][1] = f2tf32(sa[o + a8]);
            a[mi][2] = f2tf32(sa[o + a4k]);
            a[mi][3] = f2tf32(sa[o + a8 + a4k]);
        }
#pragma unroll
        for (int ni = 0; ni < 8; ni++) {
            unsigned o = bAddr[ni];
            b[ni][0] = f2tf32(sb[o]);
            b[ni][1] = f2tf32(sb[o + b4k]);
        }
#pragma unroll
        for (int mi = 0; mi < 4; mi++)
#pragma unroll
            for (int ni = 0; ni < 8; ni++)
                mma_tf32(acc[mi][ni], a[mi], b[ni]);

        __syncthreads();       // all warps done with slot (t) before refill
        if (t + 2 < nt) {
            int ns = slot + 2; if (ns >= STAGES) ns -= STAGES;
            FETCH(t + 2, ns);
        } else {
            CP_COMMIT();       // keep group accounting uniform
        }
        if (++slot == STAGES) slot = 0;
    }

    int c2 = (lane & 3) * 2;
    if (p.kSplit > 1) {
#pragma unroll
        for (int mi = 0; mi < 4; mi++) {
            int gm0 = bm + wm * 64 + mi * 16 + r;
#pragma unroll
            for (int ni = 0; ni < 8; ni++) {
                int gn = bn + wn * 64 + ni * 8 + c2;
                if (gn < p.N) {
                    atomicAdd(C + (long)gm0 * p.ldc + gn,     acc[mi][ni][0]);
                    atomicAdd(C + (long)gm0 * p.ldc + gn + 1, acc[mi][ni][1]);
                    atomicAdd(C + (long)(gm0 + 8) * p.ldc + gn,     acc[mi][ni][2]);
                    atomicAdd(C + (long)(gm0 + 8) * p.ldc + gn + 1, acc[mi][ni][3]);
                }
            }
        }
    } else {
#pragma unroll
        for (int mi = 0; mi < 4; mi++) {
            int gm0 = bm + wm * 64 + mi * 16 + r;
#pragma unroll
            for (int ni = 0; ni < 8; ni++) {
                int gn = bn + wn * 64 + ni * 8 + c2;
                if (gn < p.N) {
                    float* cp0 = C + (long)gm0 * p.ldc + gn;
                    float* cp1 = C + (long)(gm0 + 8) * p.ldc + gn;
                    cp0[0] = acc[mi][ni][0]; cp0[1] = acc[mi][ni][1];
                    cp1[0] = acc[mi][ni][2]; cp1[1] = acc[mi][ni][3];
                }
            }
        }
    }
#undef FETCH
}

// ---------------- RoPE ----------------
__global__ void rope_k_kernel(const float* __restrict__ ckr,
                              const float* __restrict__ fc,
                              const float* __restrict__ fs,
                              float* __restrict__ kcat) {
    int idx = blockIdx.x * blockDim.x + threadIdx.x;
    if (idx >= 2048 * 32) return;
    int m = idx >> 5, i = idx & 31;
    int t = m & 1023;
    float re = ckr[m * 64 + 2 * i], im = ckr[m * 64 + 2 * i + 1];
    float c = fc[t * 32 + i], s = fs[t * 32 + i];
    long o = (long)m * KCAT + 512 + 2 * i;
    kcat[o]     = re * c - im * s;
    kcat[o + 1] = re * s + im * c;
}

__global__ void rope_q_kernel(const float* __restrict__ cqr,
                              const float* __restrict__ fc,
                              const float* __restrict__ fs,
                              float* __restrict__ qcat) {
    int idx = blockIdx.x * blockDim.x + threadIdx.x;
    if (idx >= 2048 * 16 * 32) return;
    int i = idx & 31;
    int h = (idx >> 5) & 15;
    int m = idx >> 9;
    int t = m & 1023, b = m >> 10;
    float re = cqr[m * 1024 + h * 64 + 2 * i];
    float im = cqr[m * 1024 + h * 64 + 2 * i + 1];
    float c = fc[t * 32 + i], s = fs[t * 32 + i];
    long o = ((long)((b * 16 + h) * 1024 + t)) * KCAT + 512 + 2 * i;
    qcat[o]     = re * c - im * s;
    qcat[o + 1] = re * s + im * c;
}

// ---------------- causal softmax ----------------
__global__ void softmax_causal(float* __restrict__ attn) {
    int t = blockIdx.x;
    int z = blockIdx.y;
    float* p = attn + (long)z * 1024 * 1024 + (long)t * 1024;
    int n = t + 1;
    int lim = ((t >> 7) + 1) << 7;
    const float scale = 0.07216878364870322992f * 1.44269504088896341f;
    __shared__ float red[256];
    int tid = threadIdx.x;

    float vals[4];
    float m = -3.4e38f;
#pragma unroll
    for (int j = 0; j < 4; j++) {
        int s = tid + j * 256;
        vals[j] = (s < n) ? p[s] * scale : -3.4e38f;
        m = fmaxf(m, vals[j]);
    }
    red[tid] = m; __syncthreads();
    for (int o = 128; o > 0; o >>= 1) {
        if (tid < o) red[tid] = fmaxf(red[tid], red[tid + o]);
        __syncthreads();
    }
    m = red[0]; __syncthreads();

    float sum = 0.f;
#pragma unroll
    for (int j = 0; j < 4; j++) {
        int s = tid + j * 256;
        vals[j] = (s < n) ? exp2f(vals[j] - m) : 0.f;
        sum += vals[j];
    }
    red[tid] = sum; __syncthreads();
    for (int o = 128; o > 0; o >>= 1) {
        if (tid < o) red[tid] += red[tid + o];
        __syncthreads();
    }
    float inv = 1.f / red[0];

#pragma unroll
    for (int j = 0; j < 4; j++) {
        int s = tid + j * 256;
        if (s < lim) p[s] = vals[j] * inv;
    }
}

// ---------------- launch helper ----------------
static void launch_gemm(const float* A, const float* B, float* C,
                        int M, int N, int K,
                        long sAm, long sAk, long sBk, long sBn, long ldc,
                        int batches,
                        int aDiv, long aS1, int aMod, long aS2,
                        int bDiv, long bS1, int bMod, long bS2,
                        int cDiv, long cS1, int cMod, long cS2,
                        int kSplit = 1, int mode = 0) {
    GP p;
    p.A = A; p.B = B; p.C = C;
    p.M = M; p.N = N; p.K = K;
    p.sAm = sAm; p.sAk = sAk; p.sBk = sBk; p.sBn = sBn; p.ldc = ldc;
    p.aDiv = aDiv; p.aMod = aMod; p.bDiv = bDiv; p.bMod = bMod;
    p.cDiv = cDiv; p.cMod = cMod;
    p.aS1 = aS1; p.aS2 = aS2; p.bS1 = bS1; p.bS2 = bS2; p.cS1 = cS1; p.cS2 = cS2;
    p.kSplit = kSplit; p.mode = mode;
    dim3 grid((N + 127) / 128, (M + 127) / 128, batches * kSplit);
    tgemm<<<grid, 128>>>(p);
}

extern "C" void kernel_launch(void* const* d_in, const int* in_sizes, int n_in,
                              void* d_out, int out_size) {
    const float* x     = (const float*)d_in[0];
    const float* fcos  = (const float*)d_in[1];
    const float* fsin  = (const float*)d_in[2];
    const float* W_dq  = (const float*)d_in[3];
    const float* W_uq  = (const float*)d_in[4];
    const float* W_dkv = (const float*)d_in[5];
    const float* W_uk  = (const float*)d_in[6];
    const float* W_uv  = (const float*)d_in[7];
    const float* W_qr  = (const float*)d_in[8];
    const float* W_kr  = (const float*)d_in[9];
    const float* W_o   = (const float*)d_in[10];
    float* out = (float*)d_out;

    float *keff, *veff, *cq, *ckr, *cqr, *kcat, *qcat, *attn, *lat;
    cudaGetSymbolAddress((void**)&keff, g_keff);
    cudaGetSymbolAddress((void**)&veff, g_veff);
    cudaGetSymbolAddress((void**)&cq,   g_cq);
    cudaGetSymbolAddress((void**)&ckr,  g_ckr);
    cudaGetSymbolAddress((void**)&cqr,  g_cqr);
    cudaGetSymbolAddress((void**)&kcat, g_kcat);
    cudaGetSymbolAddress((void**)&qcat, g_qcat);
    cudaGetSymbolAddress((void**)&attn, g_attn);
    cudaGetSymbolAddress((void**)&lat,  g_lat);

    cudaMemsetAsync(veff, 0, 2048l * 512 * 4);
    cudaMemsetAsync(cq,   0, 2048l * 512 * 4);
    cudaMemsetAsync(ckr,  0, 2048l * 64 * 4);
    cudaMemsetAsync(cqr,  0, 2048l * 1024 * 4);
    cudaMemsetAsync(kcat, 0, 2048l * 576 * 4);

    // 1) keff_t[h][k][q]
    launch_gemm(W_uk, W_uq, keff, 512, 512, 128,
                1, 512, 1, 2048, 512, 16,
                1, 0, 16, 128l * 512,
                1, 0, 16, 128,
                1, 0, 16, 512l * 512);

    // 2) veff_t[j][k]  (split-K 4)
    launch_gemm(W_o, W_uv, veff, 2048, 512, 2048,
                2048, 1, 512, 1, 512, 1,
                1, 0, 1, 0, 1, 0, 1, 0, 1, 0, 1, 0, 4);

    // 3) c_q  (split-K 4)
    launch_gemm(x, W_dq, cq, 2048, 512, 2048,
                2048, 1, 1, 2048, 512, 1,
                1, 0, 1, 0, 1, 0, 1, 0, 1, 0, 1, 0, 4);

    // 4) c_kv -> kcat cols [0,512)  (split-K 4)
    launch_gemm(x, W_dkv, kcat, 2048, 512, 2048,
                2048, 1, 1, 2048, KCAT, 1,
                1, 0, 1, 0, 1, 0, 1, 0, 1, 0, 1, 0, 4);

    // 5) c_kr  (split-K 8)
    launch_gemm(x, W_kr, ckr, 2048, 64, 2048,
                2048, 1, 1, 2048, 64, 1,
                1, 0, 1, 0, 1, 0, 1, 0, 1, 0, 1, 0, 8);

    // 6) c_qr  (split-K 2)
    launch_gemm(cq, W_qr, cqr, 2048, 1024, 512,
                512, 1, 1, 512, 1024, 1,
                1, 0, 1, 0, 1, 0, 1, 0, 1, 0, 1, 0, 2);

    // 7-8) RoPE
    rope_k_kernel<<<(2048 * 32 + 255) / 256, 256>>>(ckr, fcos, fsin, kcat);
    rope_q_kernel<<<(2048 * 16 * 32 + 255) / 256, 256>>>(cqr, fcos, fsin, qcat);

    // 9) q_abs (B contiguous via keff_t)
    launch_gemm(cq, keff, qcat, 1024, 512, 512,
                512, 1, 1, 512, KCAT, 32,
                16, 1024l * 512, 1, 0,
                1, 0, 16, 512l * 512,
                1, 0, 32, 1024l * KCAT);

    // 10) logits (causal tile-skip)
    launch_gemm(qcat, kcat, attn, 1024, 1024, KCAT,
                KCAT, 1, 1, KCAT, 1024, 32,
                1, 0, 32, 1024l * KCAT,
                16, 1024l * KCAT, 1, 0,
                1, 0, 32, 1024l * 1024, 1, 1);

    // 11) softmax
    {
        dim3 grid(1024, 32);
        softmax_causal<<<grid, 256>>>(attn);
    }

    // 12) lat (causal k-stop)
    launch_gemm(attn, kcat, lat, 1024, 512, 1024,
                1024, 1, KCAT, 1, 512, 32,
                1, 0, 32, 1024l * 1024,
                16, 1024l * KCAT, 1, 0,
                1, 0, 32, 1024l * 512, 1, 2);

    // 13) y = lat @ veff_t^T
    launch_gemm(lat, veff, out, 1024, 128, 512,
                512, 1, 1, 512, 2048, 32,
                1, 0, 32, 1024l * 512,
                1, 0, 16, 128l * 512,
                16, 1024l * 2048, 16, 128);
}